// round 1
// baseline (speedup 1.0000x reference)
#include <cuda_runtime.h>

// Problem constants (fixed by the dataset)
#define BB      8
#define N_GRID  4096
#define N_OFF   4096
#define DIM     2
#define DY      2

#define OSPLIT  8
#define OCHUNK  (N_OFF / OSPLIT)   // 512 off-grid points per block
#define GTILE   256                // grid points per block (= blockDim)

// Partial sums: [OSPLIT][B*N_GRID] float2. 8 * 32768 * 8B = 2 MB static scratch.
__device__ float2 g_partial[OSPLIT * BB * N_GRID];

// sqrt(0.5 * log2(e)) : folds both the -0.5 factor and the base-2 conversion
// into the coordinate prescale so the weight is a single ex2.approx.
#define KPRE 0.84932180580216862f

__global__ void __launch_bounds__(256) conv_main(
    const float* __restrict__ xo,   // [B, N_OFF, 2]
    const float* __restrict__ yo,   // [B, N_OFF, 2]
    const float* __restrict__ xg,   // [B, N_GRID, 2]
    const float* __restrict__ lsp)  // [2]
{
    __shared__ float4 tile[OCHUNK];
    __shared__ float  k01[2];

    const int b     = blockIdx.y;
    const int obase = blockIdx.z * OCHUNK;

    // lengthscale: ls = 1e-5 + softplus(p); prescale factor k = KPRE / ls
    if (threadIdx.x < 2) {
        float p  = lsp[threadIdx.x];
        float ls = 1e-5f + log1pf(expf(p));
        k01[threadIdx.x] = KPRE / ls;
    }
    __syncthreads();
    const float k0 = k01[0];
    const float k1 = k01[1];

    // Cooperative load of the off-grid chunk, prescaled, into shared.
    const float2* xo2 = (const float2*)xo + (size_t)b * N_OFF;
    const float2* yo2 = (const float2*)yo + (size_t)b * N_OFF;
    for (int i = threadIdx.x; i < OCHUNK; i += 256) {
        float2 x = xo2[obase + i];
        float2 y = yo2[obase + i];
        tile[i] = make_float4(x.x * k0, x.y * k1, y.x, y.y);
    }
    __syncthreads();

    const int g = blockIdx.x * GTILE + threadIdx.x;
    float2 xgv = ((const float2*)xg)[(size_t)b * N_GRID + g];
    const float a0 = xgv.x * k0;
    const float a1 = xgv.y * k1;

    float acc0 = 0.f, acc1 = 0.f;
#pragma unroll 8
    for (int i = 0; i < OCHUNK; i++) {
        float4 t = tile[i];           // LDS.128 broadcast (all threads same i)
        float dx = a0 - t.x;
        float dy = a1 - t.y;
        float s  = fmaf(dy, dy, dx * dx);
        float w;
        asm("ex2.approx.ftz.f32 %0, %1;" : "=f"(w) : "f"(-s));
        acc0 = fmaf(w, t.z, acc0);
        acc1 = fmaf(w, t.w, acc1);
    }

    g_partial[(size_t)(blockIdx.z * BB + b) * N_GRID + g] = make_float2(acc0, acc1);
}

// Epilogue: reduce the OSPLIT partials, copy xc and yc_on_grid, assemble output.
// Output layout (tuple flattened in return order):
//   out[0 : B*N_GRID*2)                 = xc_on_grid
//   out[B*N_GRID*2 : B*N_GRID*2 + B*N_GRID*4) = concat(yc_on_grid, gridded) per point
__global__ void __launch_bounds__(256) conv_epilogue(
    const float* __restrict__ xg,
    const float* __restrict__ yg,
    float* __restrict__ out)
{
    int idx = blockIdx.x * 256 + threadIdx.x;   // flat (b, g), 32768 total
    if (idx >= BB * N_GRID) return;

    float2 x = ((const float2*)xg)[idx];
    ((float2*)out)[idx] = x;

    float2 yon = ((const float2*)yg)[idx];
    float sx = 0.f, sy = 0.f;
#pragma unroll
    for (int p = 0; p < OSPLIT; p++) {
        float2 v = g_partial[(size_t)p * (BB * N_GRID) + idx];
        sx += v.x;
        sy += v.y;
    }
    float4* outy = (float4*)(out + (size_t)BB * N_GRID * 2);
    outy[idx] = make_float4(yon.x, yon.y, sx, sy);
}

extern "C" void kernel_launch(void* const* d_in, const int* in_sizes, int n_in,
                              void* d_out, int out_size) {
    const float* xo  = (const float*)d_in[0];  // xc_off_grid
    const float* yo  = (const float*)d_in[1];  // yc_off_grid
    const float* xg  = (const float*)d_in[2];  // xc_on_grid
    const float* yg  = (const float*)d_in[3];  // yc_on_grid
    const float* lsp = (const float*)d_in[4];  // lengthscale_param

    conv_main<<<dim3(N_GRID / GTILE, BB, OSPLIT), 256>>>(xo, yo, xg, lsp);
    conv_epilogue<<<(BB * N_GRID + 255) / 256, 256>>>(xg, yg, (float*)d_out);
}